// round 1
// baseline (speedup 1.0000x reference)
#include <cuda_runtime.h>

// Problem constants (fixed by setup_inputs)
#define NN   4096          // hidden dim
#define NB   512           // batch
#define NP   4224          // padded rows: 4096 + 128 (row 4096 == Z for zdot)
#define DTC  0.1f

// Scratch (__device__ globals; no allocation allowed)
__device__ __align__(256) float g_W[(size_t)NP * NN];      // W_eff, padded
__device__ __align__(256) float g_h[2 * (size_t)NP * NB];  // double-buffered state
__device__ __align__(256) float g_x[2 * 2 * NB];           // double-buffered x (2 x 512)
__device__ __align__(256) float g_q[NB];                   // q_t = DT*(C@A)@x_t

// ---------------------------------------------------------------------------
// Build W_eff[i,j] = DT*W[i,j] + DT*sum_r U[i,r]V[j,r] + (1-DT)*(i==j) + M[i]*cb*Z[j]
// Rows 4096..4223: row 4096 = Z (gives zdot), rest zero.
// ---------------------------------------------------------------------------
__global__ void prep_W(const float* __restrict__ Wr, const float* __restrict__ U,
                       const float* __restrict__ V, const float* __restrict__ M,
                       const float* __restrict__ Z, const float* __restrict__ C,
                       const float* __restrict__ Bm) {
    int j = blockIdx.x * 256 + threadIdx.x;   // 0..4095
    int i = blockIdx.y;                       // 0..4223
    size_t idx = (size_t)i * NN + j;
    if (i < NN) {
        float cb = C[0] * Bm[0] + C[1] * Bm[1];   // (C @ Bmat) scalar
        float uv = 0.f;
#pragma unroll
        for (int r = 0; r < 4; r++) uv += U[i * 4 + r] * V[j * 4 + r];
        float w = DTC * Wr[idx] + DTC * uv + M[i] * cb * Z[j];
        if (i == j) w += 1.0f - DTC;
        g_W[idx] = w;
    } else if (i == NN) {
        g_W[idx] = Z[j];
    } else {
        g_W[idx] = 0.f;
    }
}

// ---------------------------------------------------------------------------
// x_0 = [x0; x1];  q_0 = DT * (C@A) @ x_0
// ---------------------------------------------------------------------------
__global__ void init_x(const float* __restrict__ x0, const float* __restrict__ x1,
                       const float* __restrict__ A, const float* __restrict__ C) {
    int b = blockIdx.x * 256 + threadIdx.x;
    if (b >= NB) return;
    float v0 = x0[b], v1 = x1[b];
    g_x[b] = v0;
    g_x[NB + b] = v1;
    float CA0 = C[0] * A[0] + C[1] * A[2];
    float CA1 = C[0] * A[1] + C[1] * A[3];
    g_q[b] = DTC * (CA0 * v0 + CA1 * v1);
}

// ---------------------------------------------------------------------------
// After GEMM of step t: zdot_t sits in row 4096 of the freshly written buffer.
// con_t = Bm[1]*zdot; x_{t+1} = A@x_t + Bm*zdot; q_{t+1} = DT*(C@A)@x_{t+1}
// ---------------------------------------------------------------------------
__global__ void post_step(const float* __restrict__ A, const float* __restrict__ Bm,
                          const float* __restrict__ C, float* __restrict__ conOut,
                          int cur, int nxt) {
    int b = blockIdx.x * 256 + threadIdx.x;
    if (b >= NB) return;
    float zd = g_h[(size_t)nxt * NP * NB + (size_t)NN * NB + b];
    conOut[b] = Bm[1] * zd;
    float x0c = g_x[cur * 2 * NB + b];
    float x1c = g_x[cur * 2 * NB + NB + b];
    float nx0 = A[0] * x0c + A[1] * x1c + Bm[0] * zd;
    float nx1 = A[2] * x0c + A[3] * x1c + Bm[1] * zd;
    g_x[nxt * 2 * NB + b] = nx0;
    g_x[nxt * 2 * NB + NB + b] = nx1;
    float CA0 = C[0] * A[0] + C[1] * A[2];
    float CA1 = C[0] * A[1] + C[1] * A[3];
    g_q[b] = DTC * (CA0 * nx0 + CA1 * nx1);
}

// ---------------------------------------------------------------------------
// SGEMM: Hout(4224x512) = W_eff(4224x4096) @ Hin(4096x512) + M[i]*q[b] (i<4096)
// BM=128, BN=64, BK=16, 128 threads, 8x8 register tile per thread.
// ---------------------------------------------------------------------------
__global__ __launch_bounds__(128) void gemm_step(const float* __restrict__ Hin,
                                                 float* __restrict__ Hout,
                                                 const float* __restrict__ M) {
    __shared__ float As[16][132];   // padded to soften transpose-store conflicts
    __shared__ float Bs[16][64];

    const int tid = threadIdx.x;
    const int tx = tid & 7;         // 8 col groups
    const int ty = tid >> 3;        // 16 row groups
    const int rowBase = blockIdx.y * 128;
    const int colBase = blockIdx.x * 64;

    float acc[8][8];
#pragma unroll
    for (int m = 0; m < 8; m++)
#pragma unroll
        for (int n = 0; n < 8; n++) acc[m][n] = 0.f;

    for (int k0 = 0; k0 < NN; k0 += 16) {
        // A tile: 128 rows x 16 k  (512 float4, 4 per thread), transposed into As
#pragma unroll
        for (int l = 0; l < 4; l++) {
            int f = tid + l * 128;
            int r = f >> 2;
            int c = (f & 3) << 2;
            float4 v = *(const float4*)(g_W + (size_t)(rowBase + r) * NN + k0 + c);
            As[c + 0][r] = v.x; As[c + 1][r] = v.y;
            As[c + 2][r] = v.z; As[c + 3][r] = v.w;
        }
        // B tile: 16 k x 64 cols (256 float4, 2 per thread)
#pragma unroll
        for (int l = 0; l < 2; l++) {
            int f = tid + l * 128;
            int kr = f >> 4;
            int c = (f & 15) << 2;
            float4 v = *(const float4*)(Hin + (size_t)(k0 + kr) * NB + colBase + c);
            *(float4*)(&Bs[kr][c]) = v;
        }
        __syncthreads();
#pragma unroll
        for (int kk = 0; kk < 16; kk++) {
            float a[8], b[8];
#pragma unroll
            for (int m = 0; m < 8; m++) a[m] = As[kk][ty * 8 + m];
#pragma unroll
            for (int n = 0; n < 8; n++) b[n] = Bs[kk][tx * 8 + n];
#pragma unroll
            for (int m = 0; m < 8; m++)
#pragma unroll
                for (int n = 0; n < 8; n++) acc[m][n] += a[m] * b[n];
        }
        __syncthreads();
    }

    float qv[8];
#pragma unroll
    for (int n = 0; n < 8; n++) qv[n] = g_q[colBase + tx * 8 + n];

#pragma unroll
    for (int m = 0; m < 8; m++) {
        int i = rowBase + ty * 8 + m;
        float madd = (i < NN) ? M[i] : 0.f;
#pragma unroll
        for (int n = 0; n < 8; n += 4) {
            float4 v;
            v.x = acc[m][n + 0] + madd * qv[n + 0];
            v.y = acc[m][n + 1] + madd * qv[n + 1];
            v.z = acc[m][n + 2] + madd * qv[n + 2];
            v.w = acc[m][n + 3] + madd * qv[n + 3];
            *(float4*)(Hout + (size_t)i * NB + colBase + tx * 8 + n) = v;
        }
    }
}

// ---------------------------------------------------------------------------
// Driver: graph-capturable, allocation-free.
// Inputs: x0,x1,h0,A,Bmat,C,M,Z,U,V,W_random,num_steps
// Output: traj (steps,4098,512) then all_con (steps,1,512), flattened.
// ---------------------------------------------------------------------------
extern "C" void kernel_launch(void* const* d_in, const int* in_sizes, int n_in,
                              void* d_out, int out_size) {
    const float* x0 = (const float*)d_in[0];
    const float* x1 = (const float*)d_in[1];
    const float* h0 = (const float*)d_in[2];
    const float* A  = (const float*)d_in[3];
    const float* Bm = (const float*)d_in[4];
    const float* C  = (const float*)d_in[5];
    const float* M  = (const float*)d_in[6];
    const float* Z  = (const float*)d_in[7];
    const float* U  = (const float*)d_in[8];
    const float* V  = (const float*)d_in[9];
    const float* Wr = (const float*)d_in[10];
    float* out = (float*)d_out;

    // steps derived from out_size: per step (4098*512 traj + 512 con) = 2098688
    int steps = out_size / ((NN + 2 + 1) * NB);
    if (steps <= 0) steps = 64;

    float* hp = nullptr;
    float* xp = nullptr;
    cudaGetSymbolAddress((void**)&hp, g_h);
    cudaGetSymbolAddress((void**)&xp, g_x);

    // Build W_eff and initial state
    prep_W<<<dim3(NN / 256, NP), 256>>>(Wr, U, V, M, Z, C, Bm);
    init_x<<<2, 256>>>(x0, x1, A, C);
    cudaMemcpyAsync(hp, h0, (size_t)NN * NB * sizeof(float),
                    cudaMemcpyDeviceToDevice, 0);

    const size_t trajStride = (size_t)(NN + 2) * NB;   // 4098*512
    float* conBase = out + (size_t)steps * trajStride;

    for (int t = 0; t < steps; t++) {
        int cur = t & 1;
        int nxt = cur ^ 1;
        float* hcur = hp + (size_t)cur * NP * NB;
        float* hnxt = hp + (size_t)nxt * NP * NB;

        // traj[t] = state_t (x rows 0..1, h rows 2..4097) — both contiguous
        cudaMemcpyAsync(out + (size_t)t * trajStride, xp + cur * 2 * NB,
                        2 * NB * sizeof(float), cudaMemcpyDeviceToDevice, 0);
        cudaMemcpyAsync(out + (size_t)t * trajStride + 2 * NB, hcur,
                        (size_t)NN * NB * sizeof(float),
                        cudaMemcpyDeviceToDevice, 0);

        // h_{t+1} = W_eff @ h_t + M*q_t ; row 4096 of output = zdot_t = Z@h_t
        gemm_step<<<dim3(NB / 64, NP / 128), 128>>>(hcur, hnxt, M);

        // con_t, x_{t+1}, q_{t+1}
        post_step<<<2, 256>>>(A, Bm, C, conBase + (size_t)t * NB, cur, nxt);
    }
}

// round 3
// speedup vs baseline: 1.2481x; 1.2481x over previous
#include <cuda_runtime.h>
#include <cuda_bf16.h>
#include <mma.h>
using namespace nvcuda;

// Problem constants (fixed by setup_inputs)
#define NN   4096
#define NB   512
#define DTC  0.1f

// GEMM tiling
#define BM 128
#define BN 128
#define BK 32

// ------------------------- device scratch (no allocs) -----------------------
__device__ __align__(256) __nv_bfloat16 g_Whi[(size_t)NN * NN];
__device__ __align__(256) __nv_bfloat16 g_Wlo[(size_t)NN * NN];
__device__ __align__(256) __nv_bfloat16 g_hhi[2 * (size_t)NN * NB];
__device__ __align__(256) __nv_bfloat16 g_hlo[2 * (size_t)NN * NB];
__device__ __align__(256) float g_acc[(size_t)NN * NB];   // raw W_eff @ h
__device__ __align__(256) float g_dump[(size_t)NN * NB];  // sink for final step
__device__ float g_x[2][2 * NB];
__device__ float g_q[NB];
__device__ float g_zdot[NB];

// ---------------------------------------------------------------------------
// W_eff[i,j] = DT*W + DT*U V^T + (1-DT)I + M[i]*(C@Bmat)*Z[j], split to bf16 hi/lo
// ---------------------------------------------------------------------------
__global__ void prep_W(const float* __restrict__ Wr, const float* __restrict__ U,
                       const float* __restrict__ V, const float* __restrict__ M,
                       const float* __restrict__ Z, const float* __restrict__ C,
                       const float* __restrict__ Bm) {
    int j = blockIdx.x * 256 + threadIdx.x;
    int i = blockIdx.y;
    size_t idx = (size_t)i * NN + j;
    float cb = C[0] * Bm[0] + C[1] * Bm[1];
    float uv = 0.f;
#pragma unroll
    for (int r = 0; r < 4; r++) uv += U[i * 4 + r] * V[j * 4 + r];
    float w = DTC * Wr[idx] + DTC * uv + M[i] * cb * Z[j];
    if (i == j) w += 1.0f - DTC;
    __nv_bfloat16 hi = __float2bfloat16(w);
    g_Whi[idx] = hi;
    g_Wlo[idx] = __float2bfloat16(w - __bfloat162float(hi));
}

// x_0 = [x0;x1]; q_0 = DT*(C@A)@x_0 ; also write traj[0] x rows
__global__ void init_x(const float* __restrict__ x0, const float* __restrict__ x1,
                       const float* __restrict__ A, const float* __restrict__ C,
                       float* __restrict__ xDst0) {
    int b = blockIdx.x * 256 + threadIdx.x;
    if (b >= NB) return;
    float v0 = x0[b], v1 = x1[b];
    g_x[0][b] = v0;
    g_x[0][NB + b] = v1;
    xDst0[b] = v0;
    xDst0[NB + b] = v1;
    float CA0 = C[0] * A[0] + C[1] * A[2];
    float CA1 = C[0] * A[1] + C[1] * A[3];
    g_q[b] = DTC * (CA0 * v0 + CA1 * v1);
}

// split h0 into bf16 hi/lo (buffer 0)
__global__ void hsplit(const float* __restrict__ h0) {
    size_t idx = (size_t)blockIdx.x * 256 + threadIdx.x;
    float v = h0[idx];
    __nv_bfloat16 hi = __float2bfloat16(v);
    g_hhi[idx] = hi;
    g_hlo[idx] = __float2bfloat16(v - __bfloat162float(hi));
}

// ---------------------------------------------------------------------------
// bf16 split-precision GEMM: g_acc = Whi@hhi + Whi@hlo + Wlo@hhi   (4096x512)
// 128x128x32 tile, 8 warps, warp tile 32x64, wmma 16x16x16 bf16 -> fp32.
// ---------------------------------------------------------------------------
__global__ __launch_bounds__(256, 1) void gemm_step(
    const __nv_bfloat16* __restrict__ Bh, const __nv_bfloat16* __restrict__ Bl) {
    __shared__ __align__(32) __nv_bfloat16 Ahs[BM][BK + 8];
    __shared__ __align__(32) __nv_bfloat16 Als[BM][BK + 8];
    __shared__ __align__(32) __nv_bfloat16 Bhs[BK][BN + 8];
    __shared__ __align__(32) __nv_bfloat16 Bls[BK][BN + 8];

    const int tid = threadIdx.x;
    const int wid = tid >> 5;
    const int wm = wid >> 1;          // 0..3  (M direction, 32 rows each)
    const int wn = wid & 1;           // 0..1  (N direction, 64 cols each)
    const int rowBase = blockIdx.y * BM;
    const int colBase = blockIdx.x * BN;

    wmma::fragment<wmma::accumulator, 16, 16, 16, float> acc[2][4];
#pragma unroll
    for (int i = 0; i < 2; i++)
#pragma unroll
        for (int j = 0; j < 4; j++) wmma::fill_fragment(acc[i][j], 0.f);

    for (int k0 = 0; k0 < NN; k0 += BK) {
        // A tiles: 128x32 hi+lo. 512 float4 per matrix, 2 per thread.
#pragma unroll
        for (int l = 0; l < 2; l++) {
            int f = tid + l * 256;
            int r = f >> 2;
            int c = (f & 3) * 8;
            size_t gidx = (size_t)(rowBase + r) * NN + k0 + c;
            *(float4*)(&Ahs[r][c]) = *(const float4*)(g_Whi + gidx);
            *(float4*)(&Als[r][c]) = *(const float4*)(g_Wlo + gidx);
        }
        // B tiles: 32x128 hi+lo. 512 float4 per matrix, 2 per thread.
#pragma unroll
        for (int l = 0; l < 2; l++) {
            int f = tid + l * 256;
            int r = f >> 4;
            int c = (f & 15) * 8;
            size_t gidx = (size_t)(k0 + r) * NB + colBase + c;
            *(float4*)(&Bhs[r][c]) = *(const float4*)(Bh + gidx);
            *(float4*)(&Bls[r][c]) = *(const float4*)(Bl + gidx);
        }
        __syncthreads();

#pragma unroll
        for (int kk = 0; kk < BK; kk += 16) {
            wmma::fragment<wmma::matrix_a, 16, 16, 16, __nv_bfloat16, wmma::row_major> ah[2], al[2];
#pragma unroll
            for (int i = 0; i < 2; i++) {
                wmma::load_matrix_sync(ah[i], &Ahs[wm * 32 + i * 16][kk], BK + 8);
                wmma::load_matrix_sync(al[i], &Als[wm * 32 + i * 16][kk], BK + 8);
            }
#pragma unroll
            for (int j = 0; j < 4; j++) {
                wmma::fragment<wmma::matrix_b, 16, 16, 16, __nv_bfloat16, wmma::row_major> bh, bl;
                wmma::load_matrix_sync(bh, &Bhs[kk][wn * 64 + j * 16], BN + 8);
                wmma::load_matrix_sync(bl, &Bls[kk][wn * 64 + j * 16], BN + 8);
#pragma unroll
                for (int i = 0; i < 2; i++) {
                    wmma::mma_sync(acc[i][j], ah[i], bh, acc[i][j]);
                    wmma::mma_sync(acc[i][j], ah[i], bl, acc[i][j]);
                    wmma::mma_sync(acc[i][j], al[i], bh, acc[i][j]);
                }
            }
        }
        __syncthreads();
    }

#pragma unroll
    for (int i = 0; i < 2; i++)
#pragma unroll
        for (int j = 0; j < 4; j++) {
            size_t o = (size_t)(rowBase + wm * 32 + i * 16) * NB + colBase + wn * 64 + j * 16;
            wmma::store_matrix_sync(g_acc + o, acc[i][j], NB, wmma::mem_row_major);
        }
}

// ---------------------------------------------------------------------------
// h_{t+1} = acc + M[i]*q_t[b]; write fp32 into traj[t+1] and bf16 hi/lo buffers
// ---------------------------------------------------------------------------
__global__ void split_step(const float* __restrict__ Mv, float* __restrict__ trajDst,
                           __nv_bfloat16* __restrict__ hh, __nv_bfloat16* __restrict__ hl) {
    size_t idx = (size_t)blockIdx.x * 256 + threadIdx.x;
    int i = (int)(idx >> 9);
    int b = (int)(idx & 511);
    float v = g_acc[idx] + Mv[i] * g_q[b];
    trajDst[idx] = v;
    __nv_bfloat16 hi = __float2bfloat16(v);
    hh[idx] = hi;
    hl[idx] = __float2bfloat16(v - __bfloat162float(hi));
}

// zdot_t[b] = Z . h_t[:,b]  — 8 blocks, each owns 64 columns, full reduction
__global__ void zdot_step(const float* __restrict__ Z, const float* __restrict__ hF) {
    __shared__ float red[256];
    int c = threadIdx.x & 63;
    int lane = threadIdx.x >> 6;   // 0..3
    int b = blockIdx.x * 64 + c;
    float s = 0.f;
    for (int r = lane; r < NN; r += 4)
        s += Z[r] * hF[(size_t)r * NB + b];
    red[threadIdx.x] = s;
    __syncthreads();
    if (lane == 0)
        g_zdot[b] = red[c] + red[c + 64] + red[c + 128] + red[c + 192];
}

// con_t, x_{t+1} (also to traj[t+1]), q_{t+1}
__global__ void post_step(const float* __restrict__ A, const float* __restrict__ Bm,
                          const float* __restrict__ C, float* __restrict__ conDst,
                          float* __restrict__ xDst, int cur, int nxt) {
    int b = blockIdx.x * 256 + threadIdx.x;
    if (b >= NB) return;
    float zd = g_zdot[b];
    conDst[b] = Bm[1] * zd;
    float x0c = g_x[cur][b];
    float x1c = g_x[cur][NB + b];
    float nx0 = A[0] * x0c + A[1] * x1c + Bm[0] * zd;
    float nx1 = A[2] * x0c + A[3] * x1c + Bm[1] * zd;
    g_x[nxt][b] = nx0;
    g_x[nxt][NB + b] = nx1;
    xDst[b] = nx0;
    xDst[NB + b] = nx1;
    float CA0 = C[0] * A[0] + C[1] * A[2];
    float CA1 = C[0] * A[1] + C[1] * A[3];
    g_q[b] = DTC * (CA0 * nx0 + CA1 * nx1);
}

// ---------------------------------------------------------------------------
extern "C" void kernel_launch(void* const* d_in, const int* in_sizes, int n_in,
                              void* d_out, int out_size) {
    const float* x0 = (const float*)d_in[0];
    const float* x1 = (const float*)d_in[1];
    const float* h0 = (const float*)d_in[2];
    const float* A  = (const float*)d_in[3];
    const float* Bm = (const float*)d_in[4];
    const float* C  = (const float*)d_in[5];
    const float* M  = (const float*)d_in[6];
    const float* Z  = (const float*)d_in[7];
    const float* U  = (const float*)d_in[8];
    const float* V  = (const float*)d_in[9];
    const float* Wr = (const float*)d_in[10];
    float* out = (float*)d_out;

    int steps = out_size / ((NN + 2 + 1) * NB);
    if (steps <= 0) steps = 64;

    __nv_bfloat16* hhi = nullptr;
    __nv_bfloat16* hlo = nullptr;
    float* dump = nullptr;
    cudaGetSymbolAddress((void**)&hhi, g_hhi);
    cudaGetSymbolAddress((void**)&hlo, g_hlo);
    cudaGetSymbolAddress((void**)&dump, g_dump);

    const size_t trajStride = (size_t)(NN + 2) * NB;
    float* conBase = out + (size_t)steps * trajStride;
    const size_t hbuf = (size_t)NN * NB;

    // One-time prep
    prep_W<<<dim3(NN / 256, NN), 256>>>(Wr, U, V, M, Z, C, Bm);
    init_x<<<2, 256>>>(x0, x1, A, C, out);
    hsplit<<<NN * NB / 256, 256>>>(h0);
    cudaMemcpyAsync(out + 2 * NB, h0, hbuf * sizeof(float),
                    cudaMemcpyDeviceToDevice, 0);

    for (int t = 0; t < steps; t++) {
        int cur = t & 1;
        int nxt = cur ^ 1;
        float* hFt = out + (size_t)t * trajStride + 2 * NB;   // fp32 h_t
        bool last = (t + 1 >= steps);
        float* trajNext = last ? dump : out + (size_t)(t + 1) * trajStride + 2 * NB;
        float* xNext    = last ? dump : out + (size_t)(t + 1) * trajStride;

        // acc = W_eff @ h_t  (bf16-split, 3 tensor passes)
        gemm_step<<<dim3(NB / BN, NN / BM), 256>>>(hhi + cur * hbuf, hlo + cur * hbuf);
        // h_{t+1} = acc + M*q_t -> traj[t+1] fp32 + bf16 hi/lo
        split_step<<<NN * NB / 256, 256>>>(M, trajNext, hhi + nxt * hbuf, hlo + nxt * hbuf);
        // zdot_t = Z @ h_t ; then con_t, x_{t+1}, q_{t+1}
        zdot_step<<<8, 256>>>(Z, hFt);
        post_step<<<2, 256>>>(A, Bm, C, conBase + (size_t)t * NB, xNext, cur, nxt);
    }
}

// round 11
// speedup vs baseline: 2.2588x; 1.8097x over previous
#include <cuda_runtime.h>
#include <cuda_bf16.h>
#include <mma.h>
#include <cstdint>
using namespace nvcuda;

// Problem constants
#define NN   4096
#define NB   512
#define NP   4224          // 4096 + 128 pad rows (row 4096 = Z for zdot)
#define DTC  0.1f

// GEMM tiling
#define BM 128
#define BN 128
#define BK 32
#define NCHUNK (NN / BK)   // 128
#define STAGES 3

// smem strides (elems) and layout (bytes)
#define A_STR 40
#define B_STR 136
#define A_BYTES (BM * A_STR * 2)              // 10240
#define B_BYTES (BK * B_STR * 2)              // 8704
#define ST_AH 0
#define ST_AL A_BYTES
#define ST_BH (2 * A_BYTES)
#define ST_BL (2 * A_BYTES + B_BYTES)
#define STAGE_BYTES (2 * A_BYTES + 2 * B_BYTES)   // 37888
#define SMEM_DYN (STAGES * STAGE_BYTES)           // 113664
#define C_STR 132                                 // epilogue fp32 tile stride

// ------------------------- device scratch (no allocs) -----------------------
__device__ __align__(256) __nv_bfloat16 g_Whi[(size_t)NP * NN];
__device__ __align__(256) __nv_bfloat16 g_Wlo[(size_t)NP * NN];
__device__ __align__(256) __nv_bfloat16 g_hhi[2][(size_t)NN * NB];  // [i][b]
__device__ __align__(256) __nv_bfloat16 g_hlo[2][(size_t)NN * NB];
__device__ __align__(256) float g_dump[(size_t)NN * NB];
__device__ float g_x[2][2 * NB];
__device__ float g_q[2][NB];

__device__ __forceinline__ void cpasync16(uint32_t dst, const void* src) {
    asm volatile("cp.async.cg.shared.global [%0], [%1], 16;\n" :: "r"(dst), "l"(src));
}
#define CP_COMMIT() asm volatile("cp.async.commit_group;\n" ::: "memory")
#define CP_WAIT(n)  asm volatile("cp.async.wait_group %0;\n" :: "n"(n) : "memory")

// ---------------------------------------------------------------------------
// prep: W_eff hi/lo split; padded rows (row 4096 = Z, rest 0)
// ---------------------------------------------------------------------------
__global__ void prep_W(const float* __restrict__ Wr, const float* __restrict__ U,
                       const float* __restrict__ V, const float* __restrict__ M,
                       const float* __restrict__ Z, const float* __restrict__ C,
                       const float* __restrict__ Bm) {
    int j = blockIdx.x * 256 + threadIdx.x;
    int i = blockIdx.y;
    size_t idx = (size_t)i * NN + j;
    float w;
    if (i < NN) {
        float cb = C[0] * Bm[0] + C[1] * Bm[1];
        float uv = 0.f;
#pragma unroll
        for (int r = 0; r < 4; r++) uv += U[i * 4 + r] * V[j * 4 + r];
        w = DTC * Wr[idx] + DTC * uv + M[i] * cb * Z[j];
        if (i == j) w += 1.0f - DTC;
    } else if (i == NN) {
        w = Z[j];
    } else {
        w = 0.f;
    }
    __nv_bfloat16 hi = __float2bfloat16(w);
    g_Whi[idx] = hi;
    g_Wlo[idx] = __float2bfloat16(w - __bfloat162float(hi));
}

// x_0 = [x0;x1]; q_0 = DT*(C@A)@x_0 ; traj[0] x rows
__global__ void init_x(const float* __restrict__ x0, const float* __restrict__ x1,
                       const float* __restrict__ A, const float* __restrict__ C,
                       float* __restrict__ xDst0) {
    int b = blockIdx.x * 256 + threadIdx.x;
    if (b >= NB) return;
    float v0 = x0[b], v1 = x1[b];
    g_x[0][b] = v0;
    g_x[0][NB + b] = v1;
    xDst0[b] = v0;
    xDst0[NB + b] = v1;
    float CA0 = C[0] * A[0] + C[1] * A[2];
    float CA1 = C[0] * A[1] + C[1] * A[3];
    g_q[0][b] = DTC * (CA0 * v0 + CA1 * v1);
}

// split h0 -> bf16 hi/lo buffer 0 ([i][b] layout, no transpose needed)
__global__ void hsplit(const float* __restrict__ h0) {
    size_t idx = (size_t)blockIdx.x * 256 + threadIdx.x;
    float v = h0[idx];
    __nv_bfloat16 hi = __float2bfloat16(v);
    g_hhi[0][idx] = hi;
    g_hlo[0][idx] = __float2bfloat16(v - __bfloat162float(hi));
}

// ---------------------------------------------------------------------------
// Fused pipelined wmma GEMM step (one kernel does everything per step):
//   acc[4224,512] = Whi@hhi + Whi@hlo + Wlo@hhi  (fp32)
//   rows<4096: v = acc + M[i]*q[b] -> traj[t+1] fp32 + hhi/hlo bf16
//   row 4096 tile (blockIdx.y==32): zdot -> con_t, x_{t+1}, q_{t+1}
// ---------------------------------------------------------------------------
__device__ __forceinline__ void load_stage(uint32_t sb, int tid, int kc, int stage,
        int rowBase, int colBase,
        const __nv_bfloat16* __restrict__ Bh, const __nv_bfloat16* __restrict__ Bl) {
    uint32_t base = sb + stage * STAGE_BYTES;
    int k0 = kc * BK;
    // A hi/lo: 128x32 bf16 = 512 16B-chunks each; 2 per thread
#pragma unroll
    for (int l = 0; l < 2; l++) {
        int ch = tid + l * 256;
        int r = ch >> 2, c4 = ch & 3;
        uint32_t so = (uint32_t)(r * A_STR + c4 * 8) * 2;
        size_t go = (size_t)(rowBase + r) * NN + k0 + c4 * 8;
        cpasync16(base + ST_AH + so, g_Whi + go);
        cpasync16(base + ST_AL + so, g_Wlo + go);
    }
    // B hi/lo: 32x128 bf16 = 512 chunks each; 2 per thread
#pragma unroll
    for (int l = 0; l < 2; l++) {
        int ch = tid + l * 256;
        int kr = ch >> 4, cc = ch & 15;
        uint32_t so = (uint32_t)(kr * B_STR + cc * 8) * 2;
        size_t go = (size_t)(k0 + kr) * NB + colBase + cc * 8;
        cpasync16(base + ST_BH + so, Bh + go);
        cpasync16(base + ST_BL + so, Bl + go);
    }
    CP_COMMIT();
}

__global__ __launch_bounds__(256, 1) void gemm_step(
    const __nv_bfloat16* __restrict__ Bh, const __nv_bfloat16* __restrict__ Bl,
    __nv_bfloat16* __restrict__ hhN, __nv_bfloat16* __restrict__ hlN,
    float* __restrict__ trajH, float* __restrict__ xDst,
    float* __restrict__ conDst, const float* __restrict__ Mv,
    const float* __restrict__ A, const float* __restrict__ Bm,
    const float* __restrict__ C, int cur, int nxt) {
    extern __shared__ __align__(128) char smem[];
    const int tid = threadIdx.x;
    const int wid = tid >> 5;
    const int wm = wid >> 1;          // 0..3: 32-row band
    const int wn = wid & 1;           // 0..1: 64-col band
    const int colBase = blockIdx.x * BN;
    const int rowBase = blockIdx.y * BM;
    const bool zTile = (rowBase >= NN);
    uint32_t sb = (uint32_t)__cvta_generic_to_shared(smem);

    wmma::fragment<wmma::accumulator, 16, 16, 16, float> acc[2][4];
#pragma unroll
    for (int i = 0; i < 2; i++)
#pragma unroll
        for (int j = 0; j < 4; j++) wmma::fill_fragment(acc[i][j], 0.f);

    load_stage(sb, tid, 0, 0, rowBase, colBase, Bh, Bl);
    load_stage(sb, tid, 1, 1, rowBase, colBase, Bh, Bl);

    for (int c = 0; c < NCHUNK; c++) {
        if (c + 1 < NCHUNK) { CP_WAIT(1); } else { CP_WAIT(0); }
        __syncthreads();
        if (c + 2 < NCHUNK)
            load_stage(sb, tid, c + 2, (c + 2) % STAGES, rowBase, colBase, Bh, Bl);

        char* st = smem + (c % STAGES) * STAGE_BYTES;
        __nv_bfloat16* Ahs = (__nv_bfloat16*)(st + ST_AH);
        __nv_bfloat16* Als = (__nv_bfloat16*)(st + ST_AL);
        __nv_bfloat16* Bhs = (__nv_bfloat16*)(st + ST_BH);
        __nv_bfloat16* Bls = (__nv_bfloat16*)(st + ST_BL);

#pragma unroll
        for (int kk = 0; kk < BK; kk += 16) {
            wmma::fragment<wmma::matrix_a, 16, 16, 16, __nv_bfloat16, wmma::row_major> ah[2], al[2];
#pragma unroll
            for (int i = 0; i < 2; i++) {
                wmma::load_matrix_sync(ah[i], Ahs + (wm * 32 + i * 16) * A_STR + kk, A_STR);
                wmma::load_matrix_sync(al[i], Als + (wm * 32 + i * 16) * A_STR + kk, A_STR);
            }
#pragma unroll
            for (int j = 0; j < 4; j++) {
                wmma::fragment<wmma::matrix_b, 16, 16, 16, __nv_bfloat16, wmma::row_major> bh, bl;
                wmma::load_matrix_sync(bh, Bhs + kk * B_STR + wn * 64 + j * 16, B_STR);
                wmma::load_matrix_sync(bl, Bls + kk * B_STR + wn * 64 + j * 16, B_STR);
#pragma unroll
                for (int i = 0; i < 2; i++) {
                    wmma::mma_sync(acc[i][j], ah[i], bh, acc[i][j]);
                    wmma::mma_sync(acc[i][j], ah[i], bl, acc[i][j]);
                    wmma::mma_sync(acc[i][j], al[i], bh, acc[i][j]);
                }
            }
        }
        __syncthreads();
    }

    // ------------------------------ epilogue --------------------------------
    float* sacc = (float*)smem;   // 128 x C_STR fp32 = 67584 B (pipeline dead)
#pragma unroll
    for (int i = 0; i < 2; i++)
#pragma unroll
        for (int j = 0; j < 4; j++)
            wmma::store_matrix_sync(sacc + (wm * 32 + i * 16) * C_STR + wn * 64 + j * 16,
                                    acc[i][j], C_STR, wmma::mem_row_major);
    __syncthreads();

    if (zTile) {
        // row 0 of this tile = global row 4096 = Z @ h_t = zdot
        if (tid < BN) {
            int b = colBase + tid;
            float zd = sacc[tid];
            conDst[b] = Bm[1] * zd;
            float x0c = g_x[cur][b];
            float x1c = g_x[cur][NB + b];
            float nx0 = A[0] * x0c + A[1] * x1c + Bm[0] * zd;
            float nx1 = A[2] * x0c + A[3] * x1c + Bm[1] * zd;
            g_x[nxt][b] = nx0;
            g_x[nxt][NB + b] = nx1;
            xDst[b] = nx0;
            xDst[NB + b] = nx1;
            float CA0 = C[0] * A[0] + C[1] * A[2];
            float CA1 = C[0] * A[1] + C[1] * A[3];
            g_q[nxt][b] = DTC * (CA0 * nx0 + CA1 * nx1);
        }
    } else {
        for (int e = tid; e < BM * BN; e += 256) {
            int i = e >> 7;         // 0..127
            int b = e & 127;
            float v = sacc[i * C_STR + b] + Mv[rowBase + i] * g_q[cur][colBase + b];
            size_t o = (size_t)(rowBase + i) * NB + colBase + b;
            trajH[o] = v;
            __nv_bfloat16 hi = __float2bfloat16(v);
            hhN[o] = hi;
            hlN[o] = __float2bfloat16(v - __bfloat162float(hi));
        }
    }
}

// ---------------------------------------------------------------------------
extern "C" void kernel_launch(void* const* d_in, const int* in_sizes, int n_in,
                              void* d_out, int out_size) {
    const float* x0 = (const float*)d_in[0];
    const float* x1 = (const float*)d_in[1];
    const float* h0 = (const float*)d_in[2];
    const float* A  = (const float*)d_in[3];
    const float* Bm = (const float*)d_in[4];
    const float* C  = (const float*)d_in[5];
    const float* M  = (const float*)d_in[6];
    const float* Z  = (const float*)d_in[7];
    const float* U  = (const float*)d_in[8];
    const float* V  = (const float*)d_in[9];
    const float* Wr = (const float*)d_in[10];
    float* out = (float*)d_out;

    int steps = out_size / ((NN + 2 + 1) * NB);
    if (steps <= 0) steps = 64;

    cudaFuncSetAttribute(gemm_step, cudaFuncAttributeMaxDynamicSharedMemorySize, SMEM_DYN);

    __nv_bfloat16* hh = nullptr;
    __nv_bfloat16* hl = nullptr;
    float* dump = nullptr;
    cudaGetSymbolAddress((void**)&hh, g_hhi);
    cudaGetSymbolAddress((void**)&hl, g_hlo);
    cudaGetSymbolAddress((void**)&dump, g_dump);

    const size_t trajStride = (size_t)(NN + 2) * NB;
    float* conBase = out + (size_t)steps * trajStride;
    const size_t hbuf = (size_t)NN * NB;

    // one-time prep
    prep_W<<<dim3(NN / 256, NP), 256>>>(Wr, U, V, M, Z, C, Bm);
    init_x<<<2, 256>>>(x0, x1, A, C, out);
    hsplit<<<NN * NB / 256, 256>>>(h0);
    cudaMemcpyAsync(out + 2 * NB, h0, hbuf * sizeof(float),
                    cudaMemcpyDeviceToDevice, 0);

    for (int t = 0; t < steps; t++) {
        int cur = t & 1;
        int nxt = cur ^ 1;
        bool last = (t + 1 >= steps);
        float* trajNext = last ? dump : out + (size_t)(t + 1) * trajStride + 2 * NB;
        float* xNext    = last ? dump : out + (size_t)(t + 1) * trajStride;

        gemm_step<<<dim3(NB / BN, NP / BM), 256, SMEM_DYN>>>(
            hh + cur * hbuf, hl + cur * hbuf,
            hh + nxt * hbuf, hl + nxt * hbuf,
            trajNext, xNext, conBase + (size_t)t * NB,
            M, A, Bm, C, cur, nxt);
    }
}